// round 8
// baseline (speedup 1.0000x reference)
#include <cuda_runtime.h>
#include <math.h>

#define BN 512
#define TD 2048
#define SD 768
#define HD 128

typedef unsigned long long ull;

// Scratch (device globals — no allocations allowed)
__device__ float g_tpp[32 * BN * HD];   // teacher proj partials (KLEN=64)
__device__ float g_spp[12 * BN * HD];   // student proj partials
__device__ float g_tp[BN * HD];
__device__ float g_sp[BN * HD];
// Transposed U/V: [h][row]
__device__ float g_UtT[HD * BN];
__device__ float g_VtT[HD * BN];
__device__ float g_UsT[HD * BN];
__device__ float g_VsT[HD * BN];

// ---- packed f32x2 helpers (sm_100+) --------------------------------------
__device__ __forceinline__ ull pk2(float a, float b) {
    ull r; asm("mov.b64 %0, {%1, %2};" : "=l"(r) : "f"(a), "f"(b)); return r;
}
__device__ __forceinline__ float2 unpk2(ull v) {
    float2 r; asm("mov.b64 {%0, %1}, %2;" : "=f"(r.x), "=f"(r.y) : "l"(v)); return r;
}
__device__ __forceinline__ void fma2(ull &acc, ull a, ull b) {
    asm("fma.rn.f32x2 %0, %1, %2, %0;" : "+l"(acc) : "l"(a), "l"(b));
}
// acc += relu(u + v) * w, fully packed.
// relu(x)*w = (x + |x|) * (w/2); wh pre-halved. Exact vs fl(relu(x)*w).
__device__ __forceinline__ void rabs(ull &acc, ull u, ull v, ull wh) {
    asm("{\n\t"
        ".reg .b64 t, ta;\n\t"
        "add.rn.f32x2 t, %1, %2;\n\t"
        "and.b64 ta, t, 0x7FFFFFFF7FFFFFFF;\n\t"
        "add.rn.f32x2 t, t, ta;\n\t"
        "fma.rn.f32x2 %0, t, %3, %0;\n\t"
        "}"
        : "+l"(acc) : "l"(u), "l"(v), "l"(wh));
}

// ---------------------------------------------------------------------------
// Projection GEMM partials. z=0 teacher (32 k-splits), z=1 student (12).
// KLEN=64, KC=32. Block: 32 rows x 128 cols, 128 threads, micro 4r x 8c.
// Also zeroes the output scalar (block (0,0,0)).
// ---------------------------------------------------------------------------
__global__ void __launch_bounds__(128)
proj_gemm(const float* __restrict__ T, const float* __restrict__ Wt,
          const float* __restrict__ S, const float* __restrict__ Ws,
          float* __restrict__ out, int out_size) {
    const int KC = 32;
    const int XP = 36;
    __shared__ __align__(16) float Xst[KC * XP];      // [k][r] transposed
    __shared__ __align__(16) float Wsm[KC * HD];      // [kk][c]

    if (blockIdx.x == 0 && blockIdx.y == 0 && blockIdx.z == 0 && threadIdx.x == 0)
        for (int i = 0; i < out_size; i++) out[i] = 0.0f;

    int z = blockIdx.z;
    int ky = blockIdx.y;
    const float* X; const float* W; float* outp; int ldx;
    if (z == 0) { X = T; W = Wt; ldx = TD; outp = g_tpp + ky * (BN * HD); }
    else {
        if (ky >= 12) return;
        X = S; W = Ws; ldx = SD; outp = g_spp + ky * (BN * HD);
    }

    int tid = threadIdx.x;        // 128
    int tx = tid & 15;            // cols tx*8..+7
    int ty = tid >> 4;            // rows ty*4..+3
    int row0 = blockIdx.x * 32;
    int k0 = ky * 64;

    ull acc[4][4];                // [colpair q][row m]
#pragma unroll
    for (int q = 0; q < 4; q++)
#pragma unroll
        for (int m = 0; m < 4; m++) acc[q][m] = 0ull;

#pragma unroll
    for (int kc = 0; kc < 64; kc += KC) {
#pragma unroll
        for (int t = 0; t < 2; t++) {
            int i4 = tid + t * 128;
            int r = i4 >> 3, k4 = (i4 & 7) * 4;
            float4 v = *reinterpret_cast<const float4*>(
                &X[(row0 + r) * ldx + k0 + kc + k4]);
            Xst[(k4 + 0) * XP + r] = v.x;
            Xst[(k4 + 1) * XP + r] = v.y;
            Xst[(k4 + 2) * XP + r] = v.z;
            Xst[(k4 + 3) * XP + r] = v.w;
        }
#pragma unroll
        for (int t = 0; t < 8; t++) {
            int i4 = tid + t * 128;
            int kk = i4 >> 5, c4 = (i4 & 31) * 4;
            float4 v = *reinterpret_cast<const float4*>(
                &W[(k0 + kc + kk) * HD + c4]);
            *reinterpret_cast<float4*>(&Wsm[kk * HD + c4]) = v;
        }
        __syncthreads();
#pragma unroll 8
        for (int kk = 0; kk < KC; kk++) {
            float4 a4 = *reinterpret_cast<const float4*>(&Xst[kk * XP + ty * 4]);
            ulonglong2 b01 = *reinterpret_cast<const ulonglong2*>(&Wsm[kk * HD + tx * 8]);
            ulonglong2 b23 = *reinterpret_cast<const ulonglong2*>(&Wsm[kk * HD + tx * 8 + 4]);
            ull a0 = pk2(a4.x, a4.x), a1 = pk2(a4.y, a4.y);
            ull a2 = pk2(a4.z, a4.z), a3 = pk2(a4.w, a4.w);
            fma2(acc[0][0], a0, b01.x); fma2(acc[0][1], a1, b01.x);
            fma2(acc[0][2], a2, b01.x); fma2(acc[0][3], a3, b01.x);
            fma2(acc[1][0], a0, b01.y); fma2(acc[1][1], a1, b01.y);
            fma2(acc[1][2], a2, b01.y); fma2(acc[1][3], a3, b01.y);
            fma2(acc[2][0], a0, b23.x); fma2(acc[2][1], a1, b23.x);
            fma2(acc[2][2], a2, b23.x); fma2(acc[2][3], a3, b23.x);
            fma2(acc[3][0], a0, b23.y); fma2(acc[3][1], a1, b23.y);
            fma2(acc[3][2], a2, b23.y); fma2(acc[3][3], a3, b23.y);
        }
        __syncthreads();
    }
#pragma unroll
    for (int m = 0; m < 4; m++) {
        int row = row0 + ty * 4 + m;
        float2 q0 = unpk2(acc[0][m]);
        float2 q1 = unpk2(acc[1][m]);
        float2 q2 = unpk2(acc[2][m]);
        float2 q3 = unpk2(acc[3][m]);
        *reinterpret_cast<float4*>(&outp[row * HD + tx * 8]) =
            make_float4(q0.x, q0.y, q1.x, q1.y);
        *reinterpret_cast<float4*>(&outp[row * HD + tx * 8 + 4]) =
            make_float4(q2.x, q2.y, q3.x, q3.y);
    }
}

// ---------------------------------------------------------------------------
// Sum proj partials + bias -> g_tp / g_sp. Grid 128 x 256 thr.
// ---------------------------------------------------------------------------
__global__ void __launch_bounds__(256)
sumtp(const float* __restrict__ bt, const float* __restrict__ bs) {
    int b = blockIdx.x;
    int teacher = (b < 64);
    int i4 = (teacher ? b : b - 64) * 256 + threadIdx.x;
    int k4 = (i4 & 31) * 4;
    const float* bias = teacher ? bt : bs;
    const float* pbase = teacher ? g_tpp : g_spp;
    int np = teacher ? 32 : 12;

    float4 a0 = *reinterpret_cast<const float4*>(&bias[k4]);
    float4 a1 = make_float4(0.f, 0.f, 0.f, 0.f);
    float4 a2 = make_float4(0.f, 0.f, 0.f, 0.f);
    float4 a3 = make_float4(0.f, 0.f, 0.f, 0.f);
    for (int p = 0; p < np; p += 4) {
        float4 v0 = *reinterpret_cast<const float4*>(&pbase[(p + 0) * (BN * HD) + i4 * 4]);
        float4 v1 = *reinterpret_cast<const float4*>(&pbase[(p + 1) * (BN * HD) + i4 * 4]);
        float4 v2 = *reinterpret_cast<const float4*>(&pbase[(p + 2) * (BN * HD) + i4 * 4]);
        float4 v3 = *reinterpret_cast<const float4*>(&pbase[(p + 3) * (BN * HD) + i4 * 4]);
        a0.x += v0.x; a0.y += v0.y; a0.z += v0.z; a0.w += v0.w;
        a1.x += v1.x; a1.y += v1.y; a1.z += v1.z; a1.w += v1.w;
        a2.x += v2.x; a2.y += v2.y; a2.z += v2.z; a2.w += v2.w;
        a3.x += v3.x; a3.y += v3.y; a3.z += v3.z; a3.w += v3.w;
    }
    float4 r = make_float4(a0.x + a1.x + a2.x + a3.x,
                           a0.y + a1.y + a2.y + a3.y,
                           a0.z + a1.z + a2.z + a3.z,
                           a0.w + a1.w + a2.w + a3.w);
    float* dst = teacher ? g_tp : g_sp;
    *reinterpret_cast<float4*>(&dst[i4 * 4]) = r;
}

// ---------------------------------------------------------------------------
// U/V projections -> TRANSPOSED outputs [h][row].
// grid (32 rowblocks of 16, 2 nets, 2 W1-halves) = 128 blocks, 128 thr.
// ---------------------------------------------------------------------------
__global__ void __launch_bounds__(128)
uv_gemm(const float* __restrict__ W1, const float* __restrict__ b1) {
    const int XS = 18;
    const int WS = 132;
    __shared__ float Xst[HD * XS];                   // [k][r], 16 rows
    __shared__ __align__(16) float Wsm[32 * WS];     // [kk][c]

    int rb = blockIdx.x;
    int net = blockIdx.y;
    int half = blockIdx.z;          // 0 = U (add b1), 1 = V
    const float* X = net ? g_sp : g_tp;
    const float* W = W1 + half * HD * HD;
    float* outT = net ? (half ? g_VsT : g_UsT) : (half ? g_VtT : g_UtT);

    int tid = threadIdx.x;
    int tx = tid & 15;
    int ty = tid >> 4;
    int r0 = rb * 16;

#pragma unroll
    for (int t = 0; t < 4; t++) {
        int i4 = tid + t * 128;
        int r = i4 >> 5, k4 = (i4 & 31) * 4;
        float4 v = *reinterpret_cast<const float4*>(&X[(r0 + r) * HD + k4]);
        Xst[(k4 + 0) * XS + r] = v.x;
        Xst[(k4 + 1) * XS + r] = v.y;
        Xst[(k4 + 2) * XS + r] = v.z;
        Xst[(k4 + 3) * XS + r] = v.w;
    }

    ull acc[2][4];
#pragma unroll
    for (int m = 0; m < 2; m++)
#pragma unroll
        for (int q = 0; q < 4; q++) acc[m][q] = 0ull;

    for (int kc = 0; kc < HD; kc += 32) {
        __syncthreads();
#pragma unroll
        for (int t = 0; t < 8; t++) {
            int i4 = tid + t * 128;
            int kk = i4 >> 5, c4 = (i4 & 31) * 4;
            *reinterpret_cast<float4*>(&Wsm[kk * WS + c4]) =
                *reinterpret_cast<const float4*>(&W[(kc + kk) * HD + c4]);
        }
        __syncthreads();
#pragma unroll 8
        for (int kk = 0; kk < 32; kk++) {
            float a0 = Xst[(kc + kk) * XS + ty * 2];
            float a1 = Xst[(kc + kk) * XS + ty * 2 + 1];
            ulonglong2 b01 = *reinterpret_cast<const ulonglong2*>(&Wsm[kk * WS + tx * 8]);
            ulonglong2 b23 = *reinterpret_cast<const ulonglong2*>(&Wsm[kk * WS + tx * 8 + 4]);
            ull ad0 = pk2(a0, a0), ad1 = pk2(a1, a1);
            fma2(acc[0][0], ad0, b01.x); fma2(acc[0][1], ad0, b01.y);
            fma2(acc[0][2], ad0, b23.x); fma2(acc[0][3], ad0, b23.y);
            fma2(acc[1][0], ad1, b01.x); fma2(acc[1][1], ad1, b01.y);
            fma2(acc[1][2], ad1, b23.x); fma2(acc[1][3], ad1, b23.y);
        }
    }

    int rbase = r0 + ty * 2;
#pragma unroll
    for (int q = 0; q < 4; q++) {
        int c = tx * 8 + q * 2;
        float2 p0 = unpk2(acc[0][q]);
        float2 p1 = unpk2(acc[1][q]);
        float bA = half ? 0.0f : b1[c];
        float bB = half ? 0.0f : b1[c + 1];
        *reinterpret_cast<float2*>(&outT[c * BN + rbase]) =
            make_float2(p0.x + bA, p1.x + bA);
        *reinterpret_cast<float2*>(&outT[(c + 1) * BN + rbase]) =
            make_float2(p0.y + bB, p1.y + bB);
    }
}

// ---------------------------------------------------------------------------
// Fused pairwise relations + sigmoid + MSE, both nets per block.
// Tile 32(i) x 32(j), grid (16, 16) = 256 blocks, 128 thr (64 per net).
// Micro 4i x 4j per thread -> 8 independent rabs chains, 2.25 instr/pos.
// V staged pre-duplicated as packed (v,v) ull pairs; h chunked by 16.
// ---------------------------------------------------------------------------
__global__ void __launch_bounds__(128)
pairwise_mse(const float* __restrict__ w2, const float* __restrict__ b2v,
             float* __restrict__ out) {
    const int HB = 16;      // h chunk
    __shared__ __align__(16) float sU[2][HB * 32];   // [net][h][i-row]
    __shared__ __align__(16) ull sVd[2][HB * 32];    // [net][h][j] dup-packed
    __shared__ ull swd[HD];                          // (w/2, w/2)
    __shared__ float sdot[2][32 * 32];
    __shared__ float sred[128];

    int tid = threadIdx.x;       // 128
    int net = tid >> 6;          // 64 threads per net
    int tt = tid & 63;
    int tx = tt & 7;             // j = jb + tx*4 + {0..3}
    int ty = tt >> 3;            // i = ib + ty*4 + {0..3}
    int jb = blockIdx.x * 32;
    int ib = blockIdx.y * 32;

    const float* UT = net ? g_UsT : g_UtT;
    const float* VT = net ? g_VsT : g_VtT;

    { float w = w2[tid] * 0.5f; swd[tid] = pk2(w, w); }   // tid covers HD=128

    ull acc[4][2];               // [j-offset][i-pair]
#pragma unroll
    for (int n = 0; n < 4; n++) { acc[n][0] = 0ull; acc[n][1] = 0ull; }

    for (int hb = 0; hb < HD; hb += HB) {
        __syncthreads();
        // stage U: 16h x 32r per net (128 f4, 2/thread)
#pragma unroll
        for (int t = 0; t < 2; t++) {
            int id = tt + t * 64;
            int h = id >> 3, r4 = (id & 7) * 4;
            *reinterpret_cast<float4*>(&sU[net][h * 32 + r4]) =
                *reinterpret_cast<const float4*>(&UT[(hb + h) * BN + ib + r4]);
        }
        // stage V dup-packed: 16h x 32j per net (2 f4/thread -> 4 STS.128)
#pragma unroll
        for (int t = 0; t < 2; t++) {
            int id = tt + t * 64;
            int h = id >> 3, c4 = (id & 7) * 4;
            float4 v = *reinterpret_cast<const float4*>(&VT[(hb + h) * BN + jb + c4]);
            ulonglong2 p0, p1;
            p0.x = pk2(v.x, v.x); p0.y = pk2(v.y, v.y);
            p1.x = pk2(v.z, v.z); p1.y = pk2(v.w, v.w);
            *reinterpret_cast<ulonglong2*>(&sVd[net][h * 32 + c4]) = p0;
            *reinterpret_cast<ulonglong2*>(&sVd[net][h * 32 + c4 + 2]) = p1;
        }
        __syncthreads();
#pragma unroll 8
        for (int hh = 0; hh < HB; hh++) {
            ulonglong2 u2 = *reinterpret_cast<const ulonglong2*>(
                &sU[net][hh * 32 + ty * 4]);
            ulonglong2 vd0 = *reinterpret_cast<const ulonglong2*>(
                &sVd[net][hh * 32 + tx * 4]);
            ulonglong2 vd1 = *reinterpret_cast<const ulonglong2*>(
                &sVd[net][hh * 32 + tx * 4 + 2]);
            ull wd = swd[hb + hh];
            rabs(acc[0][0], u2.x, vd0.x, wd); rabs(acc[0][1], u2.y, vd0.x, wd);
            rabs(acc[1][0], u2.x, vd0.y, wd); rabs(acc[1][1], u2.y, vd0.y, wd);
            rabs(acc[2][0], u2.x, vd1.x, wd); rabs(acc[2][1], u2.y, vd1.x, wd);
            rabs(acc[3][0], u2.x, vd1.y, wd); rabs(acc[3][1], u2.y, vd1.y, wd);
        }
    }

    // exchange dots
    __syncthreads();
#pragma unroll
    for (int n = 0; n < 4; n++) {
        int jl = tx * 4 + n;
        float2 x0 = unpk2(acc[n][0]);
        float2 x1 = unpk2(acc[n][1]);
        sdot[net][(ty * 4 + 0) * 32 + jl] = x0.x;
        sdot[net][(ty * 4 + 1) * 32 + jl] = x0.y;
        sdot[net][(ty * 4 + 2) * 32 + jl] = x1.x;
        sdot[net][(ty * 4 + 3) * 32 + jl] = x1.y;
    }
    __syncthreads();

    // sigmoid + MSE over the 32x32 tile (all 128 threads, 8 cells each)
    float b2 = b2v[0];
    float local = 0.0f;
#pragma unroll
    for (int c = tid; c < 1024; c += 128) {
        int il = c >> 5, jl = c & 31;
        if (ib + il != jb + jl) {   // diagonal: rel == 0 in both
            float t = sdot[0][c];
            float s = sdot[1][c];
            float rt = 1.0f / (1.0f + __expf(-(t + b2)));
            float rs = 1.0f / (1.0f + __expf(-(s + b2)));
            float d = rs - rt;
            local = fmaf(d, d, local);
        }
    }
    sred[tid] = local;
    __syncthreads();
    for (int st = 64; st > 0; st >>= 1) {
        if (tid < st) sred[tid] += sred[tid + st];
        __syncthreads();
    }
    if (tid == 0)
        atomicAdd(out, sred[0] * (1.0f / ((float)BN * (float)BN)));
}

// ---------------------------------------------------------------------------
extern "C" void kernel_launch(void* const* d_in, const int* in_sizes, int n_in,
                              void* d_out, int out_size) {
    const float* teacher = (const float*)d_in[0];
    const float* student = (const float*)d_in[1];
    const float* Wt = (const float*)d_in[2];
    const float* bt = (const float*)d_in[3];
    const float* Wsw = (const float*)d_in[4];
    const float* bs = (const float*)d_in[5];
    const float* W1 = (const float*)d_in[6];
    const float* b1 = (const float*)d_in[7];
    const float* W2 = (const float*)d_in[8];
    const float* b2 = (const float*)d_in[9];
    float* out = (float*)d_out;

    proj_gemm<<<dim3(16, 32, 2), 128>>>(teacher, Wt, student, Wsw, out, out_size);
    sumtp<<<128, 256>>>(bt, bs);
    uv_gemm<<<dim3(32, 2, 2), 128>>>(W1, b1);
    pairwise_mse<<<dim3(16, 16), 128>>>(W2, b2, out);
}